// round 2
// baseline (speedup 1.0000x reference)
#include <cuda_runtime.h>
#include <cstddef>

// MultiLayerLSTM: T=1024, B=64, C=256, H=512, 2 layers, fp32.
// Persistent kernel (128 CTAs, one per SM), per-timestep grid barrier,
// SMEM-resident weights, f32x2 packed-FMA inner loop, double-buffered
// activation staging.

#define T_    1024
#define B_    64
#define C_    256
#define H_    512
#define GRID_ 128
#define NTHR_ 256

// ---- shared memory layout (float offsets) ----
#define OFF_W   0
#define SZ_W    (16 * 1028)          // 16 gate rows x K(<=1024) floats, stride 1028
#define OFF_A0  (OFF_W + SZ_W)
#define SZ_A    (64 * 66 * 2)        // 64 k-pairs x 66 float2 (64 m + 2 pad)
#define OFF_A1  (OFF_A0 + SZ_A)
#define OFF_P   (OFF_A1 + SZ_A)
#define SZ_P    (1024 * 9)           // partials: 1024 outputs x 8 kgroups (+pad)
#define OFF_G   (OFF_P + SZ_P)
#define SZ_G    (16 * 65)            // reduced gates
#define OFF_C   (OFF_G + SZ_G)
#define SZ_C    (4 * 65)             // cell state: 4 hidden x 64 batch
#define OFF_H   (OFF_C + SZ_C)
#define SZ_H    256                  // h staging: 64 batch x 4 hidden
#define OFF_B   (OFF_H + SZ_H)
#define SMEM_FLOATS (OFF_B + 16)
#define SMEM_BYTES  (SMEM_FLOATS * 4)

static __device__ float g_y0[(size_t)T_ * B_ * H_];   // layer-0 outputs (128 MB scratch)
static __device__ int   g_bar;

__global__ void reset_kernel() {
    if (threadIdx.x == 0) g_bar = 0;
}

__device__ __forceinline__ void fma2(unsigned long long& d, unsigned long long a,
                                     unsigned long long b) {
    asm("fma.rn.f32x2 %0, %1, %2, %0;" : "+l"(d) : "l"(a), "l"(b));
}
__device__ __forceinline__ float sigf(float v) { return 1.0f / (1.0f + __expf(-v)); }

extern __shared__ float sm[];

__global__ void __launch_bounds__(NTHR_, 1) lstm_kernel(
    const float* __restrict__ x,
    const float* __restrict__ h00, const float* __restrict__ c00,
    const float* __restrict__ h01, const float* __restrict__ c01,
    const float* __restrict__ Wih0, const float* __restrict__ Whh0,
    const float* __restrict__ bih0, const float* __restrict__ bhh0,
    const float* __restrict__ Wih1, const float* __restrict__ Whh1,
    const float* __restrict__ bih1, const float* __restrict__ bhh1,
    float* out)
{
    const int tid = threadIdx.x;
    const int bid = blockIdx.x;
    const int j0  = bid * 4;           // first hidden unit owned by this CTA
    const int kg  = tid & 7;           // k-group (8-way k split)
    const int mg  = (tid >> 3) & 7;    // m-group (8 groups of 8 batch rows)
    const int ng  = tid >> 6;          // n-group (4 groups of 4 gate rows)

    float* Wsf = sm + OFF_W;
    float* AbufA = sm + OFF_A0;
    float* AbufB = sm + OFF_A1;
    float* Pp  = sm + OFF_P;
    float* Gr  = sm + OFF_G;
    float* Cs  = sm + OFF_C;
    float* Hs  = sm + OFF_H;
    float* Bs  = sm + OFF_B;

    float* yout = out;
    float* h1f  = out + (size_t)T_ * B_ * H_;
    float* c1f  = h1f + B_ * H_;
    float* h2f  = c1f + B_ * H_;
    float* c2f  = h2f + B_ * H_;

    int ep = 0;  // grid-barrier epoch (counter target)

    for (int phase = 0; phase < 2; phase++) {
        const int KX  = (phase == 0) ? C_ : H_;
        const int K   = KX + H_;
        const int NCH = K / 128;          // 6 or 8 chunks of 128 k
        const int XCH = KX / 128;         // chunks sourced from x-part
        const float* Wx    = (phase == 0) ? Wih0 : Wih1;
        const float* Wh    = (phase == 0) ? Whh0 : Whh1;
        const float* bi    = (phase == 0) ? bih0 : bih1;
        const float* bh    = (phase == 0) ? bhh0 : bhh1;
        const float* hinit = (phase == 0) ? h00 : h01;
        const float* cinit = (phase == 0) ? c00 : c01;
        float* hdst = (phase == 0) ? g_y0 : yout;
        float* hTd  = (phase == 0) ? h1f : h2f;
        float* cTd  = (phase == 0) ? c1f : c2f;

        // ---- load weight slice [16 rows][K] = [Wx | Wh] into SMEM ----
        for (int idx = tid; idx < 16 * K; idx += NTHR_) {
            const int n = idx / K, k = idx - n * K;
            const int gr = (n >> 2) * H_ + j0 + (n & 3);
            const float v = (k < KX) ? Wx[(size_t)gr * KX + k]
                                     : Wh[(size_t)gr * H_ + (k - KX)];
            Wsf[n * 1028 + k] = v;
        }
        if (tid < 16) {
            const int gr = (tid >> 2) * H_ + j0 + (tid & 3);
            Bs[tid] = bi[gr] + bh[gr];
        }
        {
            const int jj = tid >> 6, m = tid & 63;
            Cs[jj * 65 + m] = cinit[m * H_ + j0 + jj];
        }
        __syncthreads();

        for (int t = 0; t < T_; t++) {
            const float* hprev = (t == 0) ? hinit : (hdst + (size_t)(t - 1) * B_ * H_);
            const float* xsrc  = (phase == 0) ? (x + (size_t)t * B_ * C_)
                                              : (g_y0 + (size_t)t * B_ * H_);
            const int xrs = (phase == 0) ? C_ : H_;

            unsigned long long acc[8][4];
            #pragma unroll
            for (int i = 0; i < 8; i++)
                #pragma unroll
                for (int j = 0; j < 4; j++) acc[i][j] = 0ull;

            // ---- prologue: stage chunk 0 into buffer A ----
            {
                float4 v[8];
                #pragma unroll
                for (int it = 0; it < 8; it++) {
                    const int s = it * NTHR_ + tid;
                    const int p2 = s >> 6, m = s & 63;
                    const float* src; int rs, col;
                    if (0 < XCH) { src = xsrc; rs = xrs; col = 0; }
                    else         { src = hprev; rs = H_; col = 0; }
                    v[it] = *(const float4*)(src + (size_t)m * rs + col + p2 * 4);
                }
                float2* b2 = (float2*)AbufA;
                #pragma unroll
                for (int it = 0; it < 8; it++) {
                    const int s = it * NTHR_ + tid;
                    const int p2 = s >> 6, m = s & 63;
                    b2[(2 * p2) * 66 + m]     = make_float2(v[it].x, v[it].y);
                    b2[(2 * p2 + 1) * 66 + m] = make_float2(v[it].z, v[it].w);
                }
            }

            for (int c = 0; c < NCH; c++) {
                __syncthreads();   // current buffer ready; other buffer free

                // prefetch chunk c+1 (loads only; stores after compute)
                float4 v[8];
                const bool pf = (c + 1 < NCH);
                if (pf) {
                    const int cn = c + 1;
                    const float* src; int rs, col;
                    if (cn < XCH) { src = xsrc;  rs = xrs; col = cn * 128; }
                    else          { src = hprev; rs = H_;  col = (cn - XCH) * 128; }
                    #pragma unroll
                    for (int it = 0; it < 8; it++) {
                        const int s = it * NTHR_ + tid;
                        const int p2 = s >> 6, m = s & 63;
                        v[it] = *(const float4*)(src + (size_t)m * rs + col + p2 * 4);
                    }
                }

                // ---- compute: 64 k-pairs in this chunk, 8 per k-group ----
                {
                    const float* buf = (c & 1) ? AbufB : AbufA;
                    const unsigned long long* A8 =
                        (const unsigned long long*)buf + kg * 66 + mg;
                    const unsigned long long* W8 =
                        (const unsigned long long*)Wsf;
                    const int wb = c * 64 + kg;
                    const unsigned long long* W0 = W8 + (ng * 4 + 0) * 514 + wb;
                    const unsigned long long* W1 = W8 + (ng * 4 + 1) * 514 + wb;
                    const unsigned long long* W2 = W8 + (ng * 4 + 2) * 514 + wb;
                    const unsigned long long* W3 = W8 + (ng * 4 + 3) * 514 + wb;
                    #pragma unroll 4
                    for (int i = 0; i < 8; i++) {
                        unsigned long long a0 = A8[0],  a1 = A8[8],  a2 = A8[16], a3 = A8[24];
                        unsigned long long a4 = A8[32], a5 = A8[40], a6 = A8[48], a7 = A8[56];
                        unsigned long long w0 = W0[i * 8], w1 = W1[i * 8];
                        unsigned long long w2 = W2[i * 8], w3 = W3[i * 8];
                        fma2(acc[0][0], a0, w0); fma2(acc[1][0], a1, w0);
                        fma2(acc[2][0], a2, w0); fma2(acc[3][0], a3, w0);
                        fma2(acc[4][0], a4, w0); fma2(acc[5][0], a5, w0);
                        fma2(acc[6][0], a6, w0); fma2(acc[7][0], a7, w0);
                        fma2(acc[0][1], a0, w1); fma2(acc[1][1], a1, w1);
                        fma2(acc[2][1], a2, w1); fma2(acc[3][1], a3, w1);
                        fma2(acc[4][1], a4, w1); fma2(acc[5][1], a5, w1);
                        fma2(acc[6][1], a6, w1); fma2(acc[7][1], a7, w1);
                        fma2(acc[0][2], a0, w2); fma2(acc[1][2], a1, w2);
                        fma2(acc[2][2], a2, w2); fma2(acc[3][2], a3, w2);
                        fma2(acc[4][2], a4, w2); fma2(acc[5][2], a5, w2);
                        fma2(acc[6][2], a6, w2); fma2(acc[7][2], a7, w2);
                        fma2(acc[0][3], a0, w3); fma2(acc[1][3], a1, w3);
                        fma2(acc[2][3], a2, w3); fma2(acc[3][3], a3, w3);
                        fma2(acc[4][3], a4, w3); fma2(acc[5][3], a5, w3);
                        fma2(acc[6][3], a6, w3); fma2(acc[7][3], a7, w3);
                        A8 += 528;
                    }
                }

                // store prefetched chunk into the other buffer
                if (pf) {
                    float2* b2 = (float2*)((c & 1) ? AbufA : AbufB);
                    #pragma unroll
                    for (int it = 0; it < 8; it++) {
                        const int s = it * NTHR_ + tid;
                        const int p2 = s >> 6, m = s & 63;
                        b2[(2 * p2) * 66 + m]     = make_float2(v[it].x, v[it].y);
                        b2[(2 * p2 + 1) * 66 + m] = make_float2(v[it].z, v[it].w);
                    }
                }
            }
            __syncthreads();

            // ---- fold f32x2 lanes, write partials ----
            #pragma unroll
            for (int mm = 0; mm < 8; mm++)
                #pragma unroll
                for (int nn = 0; nn < 4; nn++) {
                    const unsigned long long a = acc[mm][nn];
                    const float lo = __uint_as_float((unsigned)(a & 0xffffffffull));
                    const float hi = __uint_as_float((unsigned)(a >> 32));
                    const int n = ng * 4 + nn;
                    const int m = mg + 8 * mm;
                    Pp[(n * 64 + m) * 9 + kg] = lo + hi;
                }
            __syncthreads();

            // ---- reduce 8 k-groups + bias ----
            #pragma unroll
            for (int r = 0; r < 4; r++) {
                const int slot = r * NTHR_ + tid;
                const int n = slot >> 6, m = slot & 63;
                float s = Bs[n];
                #pragma unroll
                for (int q = 0; q < 8; q++) s += Pp[slot * 9 + q];
                Gr[n * 65 + m] = s;
            }
            __syncthreads();

            // ---- pointwise: gates -> c, h ----
            {
                const int jj = tid >> 6, m = tid & 63;
                const float gi = sigf(Gr[jj * 65 + m]);
                const float gf = sigf(Gr[(4 + jj) * 65 + m]);
                const float gc = tanhf(Gr[(8 + jj) * 65 + m]);
                const float go = sigf(Gr[(12 + jj) * 65 + m]);
                const float cv = gf * Cs[jj * 65 + m] + gi * gc;
                Cs[jj * 65 + m] = cv;
                const float hv = go * tanhf(cv);
                Hs[m * 4 + jj] = hv;
                if (t == T_ - 1) cTd[(size_t)m * H_ + j0 + jj] = cv;
            }
            __syncthreads();

            // ---- write h slice to global ----
            if (tid < 64) {
                const float4 hv = *(const float4*)&Hs[tid * 4];
                *(float4*)(hdst + (size_t)t * B_ * H_ + (size_t)tid * H_ + j0) = hv;
                if (t == T_ - 1)
                    *(float4*)(hTd + (size_t)tid * H_ + j0) = hv;
            }

            // ---- grid barrier ----
            __syncthreads();
            if (tid == 0) {
                ep += GRID_;
                __threadfence();
                atomicAdd(&g_bar, 1);
                while (*((volatile int*)&g_bar) < ep) { }
                __threadfence();
            }
            __syncthreads();
            if (tid != 0) ep += GRID_;   // keep epoch uniform (unused off-thread0)
        }
    }
}

extern "C" void kernel_launch(void* const* d_in, const int* in_sizes, int n_in,
                              void* d_out, int out_size) {
    (void)in_sizes; (void)n_in; (void)out_size;
    cudaFuncSetAttribute(lstm_kernel, cudaFuncAttributeMaxDynamicSharedMemorySize,
                         SMEM_BYTES);
    reset_kernel<<<1, 32>>>();
    lstm_kernel<<<GRID_, NTHR_, SMEM_BYTES>>>(
        (const float*)d_in[0],
        (const float*)d_in[1], (const float*)d_in[2],
        (const float*)d_in[3], (const float*)d_in[4],
        (const float*)d_in[5], (const float*)d_in[6],
        (const float*)d_in[7], (const float*)d_in[8],
        (const float*)d_in[9], (const float*)d_in[10],
        (const float*)d_in[11], (const float*)d_in[12],
        (float*)d_out);
}

// round 3
// speedup vs baseline: 1.1685x; 1.1685x over previous
#include <cuda_runtime.h>
#include <cstddef>

// MultiLayerLSTM: T=1024, B=64, C=256, H=512, 2 layers, fp32.
// Persistent kernel (128 CTAs), per-timestep grid barrier, SMEM-resident
// weights, f32x2 packed-FMA, 8m x 8n thread tile, 16-way k-split,
// coalesced chunked activation staging with double buffering.

#define T_    1024
#define B_    64
#define C_    256
#define H_    512
#define GRID_ 128
#define NTHR_ 256
#define KC_   64          // k per staged chunk
#define KP_   32          // k-pairs per chunk

// ---- shared memory layout (float offsets) ----
#define OFF_W   0
#define SZ_W    (16 * 1028)          // 16 gate rows x K(<=1024), f32x2 row stride 514
#define OFF_A0  (OFF_W + SZ_W)
#define SZ_A    (KP_ * 65 * 2)       // 32 k-pairs x 65 f32x2 (64 m + 1 pad)
#define OFF_A1  (OFF_A0 + SZ_A)
#define OFF_P   (OFF_A1 + SZ_A)
#define SZ_P    (1024 * 17)          // partials: 1024 outputs x 16 kgroups (+pad)
#define OFF_G   (OFF_P + SZ_P)
#define SZ_G    (16 * 65)
#define OFF_C   (OFF_G + SZ_G)
#define SZ_C    (4 * 65)
#define OFF_H   (OFF_C + SZ_C)
#define SZ_H    256
#define OFF_B   (OFF_H + SZ_H)
#define SMEM_FLOATS (OFF_B + 16)
#define SMEM_BYTES  (SMEM_FLOATS * 4)

static __device__ float g_y0[(size_t)T_ * B_ * H_];   // layer-0 outputs (128 MB scratch)
static __device__ int   g_bar;

__global__ void reset_kernel() {
    if (threadIdx.x == 0) g_bar = 0;
}

__device__ __forceinline__ void fma2(unsigned long long& d, unsigned long long a,
                                     unsigned long long b) {
    asm("fma.rn.f32x2 %0, %1, %2, %0;" : "+l"(d) : "l"(a), "l"(b));
}
__device__ __forceinline__ float sigf(float v) { return 1.0f / (1.0f + __expf(-v)); }

extern __shared__ float sm[];

__global__ void __launch_bounds__(NTHR_, 1) lstm_kernel(
    const float* __restrict__ x,
    const float* __restrict__ h00, const float* __restrict__ c00,
    const float* __restrict__ h01, const float* __restrict__ c01,
    const float* __restrict__ Wih0, const float* __restrict__ Whh0,
    const float* __restrict__ bih0, const float* __restrict__ bhh0,
    const float* __restrict__ Wih1, const float* __restrict__ Whh1,
    const float* __restrict__ bih1, const float* __restrict__ bhh1,
    float* out)
{
    const int tid = threadIdx.x;
    const int bid = blockIdx.x;
    const int j0  = bid * 4;           // first hidden unit owned by this CTA
    const int kg  = tid & 15;          // k-group (16-way k split)
    const int mg  = (tid >> 4) & 7;    // m-group (8 groups of 8 batch rows)
    const int ng  = tid >> 7;          // n-group (2 groups of 8 gate rows)

    float* Wsf   = sm + OFF_W;
    float* AbufA = sm + OFF_A0;
    float* AbufB = sm + OFF_A1;
    float* Pp    = sm + OFF_P;
    float* Gr    = sm + OFF_G;
    float* Cs    = sm + OFF_C;
    float* Hs    = sm + OFF_H;
    float* Bs    = sm + OFF_B;

    float* yout = out;
    float* h1f  = out + (size_t)T_ * B_ * H_;
    float* c1f  = h1f + B_ * H_;
    float* h2f  = c1f + B_ * H_;
    float* c2f  = h2f + B_ * H_;

    int ep = 0;  // grid-barrier epoch

    for (int phase = 0; phase < 2; phase++) {
        const int KX  = (phase == 0) ? C_ : H_;
        const int K   = KX + H_;
        const int NCH = K / KC_;          // 12 or 16 chunks
        const int XCH = KX / KC_;         // chunks sourced from x-part
        const float* Wx    = (phase == 0) ? Wih0 : Wih1;
        const float* Wh    = (phase == 0) ? Whh0 : Whh1;
        const float* bi    = (phase == 0) ? bih0 : bih1;
        const float* bh    = (phase == 0) ? bhh0 : bhh1;
        const float* hinit = (phase == 0) ? h00 : h01;
        const float* cinit = (phase == 0) ? c00 : c01;
        float* hdst = (phase == 0) ? g_y0 : yout;
        float* hTd  = (phase == 0) ? h1f : h2f;
        float* cTd  = (phase == 0) ? c1f : c2f;

        // ---- load weight slice [16 rows][K] = [Wx | Wh] into SMEM ----
        for (int idx = tid; idx < 16 * K; idx += NTHR_) {
            const int n = idx / K, k = idx - n * K;
            const int gr = (n >> 2) * H_ + j0 + (n & 3);
            const float v = (k < KX) ? Wx[(size_t)gr * KX + k]
                                     : Wh[(size_t)gr * H_ + (k - KX)];
            Wsf[n * 1028 + k] = v;
        }
        if (tid < 16) {
            const int gr = (tid >> 2) * H_ + j0 + (tid & 3);
            Bs[tid] = bi[gr] + bh[gr];
        }
        {
            const int jj = tid >> 6, m = tid & 63;
            Cs[jj * 65 + m] = cinit[m * H_ + j0 + jj];
        }
        __syncthreads();

        for (int t = 0; t < T_; t++) {
            const float* hprev = (t == 0) ? hinit : (hdst + (size_t)(t - 1) * B_ * H_);
            const float* xsrc  = (phase == 0) ? (x + (size_t)t * B_ * C_)
                                              : (g_y0 + (size_t)t * B_ * H_);
            const int xrs = (phase == 0) ? C_ : H_;

            unsigned long long acc[64];
            #pragma unroll
            for (int i = 0; i < 64; i++) acc[i] = 0ull;

            // ---- prologue: stage chunk 0 into buffer A (coalesced: lanes along k) ----
            {
                float4 v[4];
                #pragma unroll
                for (int it = 0; it < 4; it++) {
                    const int s = it * NTHR_ + tid;
                    const int k4 = s & 15, m = s >> 4;
                    const float* src = (0 < XCH) ? xsrc : hprev;
                    const int rs = (0 < XCH) ? xrs : H_;
                    v[it] = *(const float4*)(src + (size_t)m * rs + k4 * 4);
                }
                float2* b2 = (float2*)AbufA;
                #pragma unroll
                for (int it = 0; it < 4; it++) {
                    const int s = it * NTHR_ + tid;
                    const int k4 = s & 15, m = s >> 4;
                    b2[(2 * k4) * 65 + m]     = make_float2(v[it].x, v[it].y);
                    b2[(2 * k4 + 1) * 65 + m] = make_float2(v[it].z, v[it].w);
                }
            }

            for (int c = 0; c < NCH; c++) {
                __syncthreads();   // current buffer ready; other buffer free

                // prefetch chunk c+1 (loads only; stores after compute)
                float4 v[4];
                const bool pf = (c + 1 < NCH);
                if (pf) {
                    const int cn = c + 1;
                    const float* src; int rs, col;
                    if (cn < XCH) { src = xsrc;  rs = xrs; col = cn * KC_; }
                    else          { src = hprev; rs = H_;  col = (cn - XCH) * KC_; }
                    #pragma unroll
                    for (int it = 0; it < 4; it++) {
                        const int s = it * NTHR_ + tid;
                        const int k4 = s & 15, m = s >> 4;
                        v[it] = *(const float4*)(src + (size_t)m * rs + col + k4 * 4);
                    }
                }

                // ---- compute: 32 k-pairs in chunk, 2 per thread (i=0,1) ----
                {
                    const unsigned long long* Ab =
                        (const unsigned long long*)((c & 1) ? AbufB : AbufA);
                    const unsigned long long* Wp =
                        (const unsigned long long*)Wsf;   // row stride 514 f32x2
                    #pragma unroll
                    for (int i = 0; i < 2; i++) {
                        const int kp = i * 16 + kg;
                        const unsigned long long* Ar = Ab + kp * 65 + mg * 8;
                        unsigned long long a0 = Ar[0], a1 = Ar[1], a2 = Ar[2], a3 = Ar[3];
                        unsigned long long a4 = Ar[4], a5 = Ar[5], a6 = Ar[6], a7 = Ar[7];
                        const unsigned long long* Wr = Wp + (ng * 8) * 514 + c * KP_ + kp;
                        unsigned long long w[8];
                        #pragma unroll
                        for (int nn = 0; nn < 8; nn++) w[nn] = Wr[nn * 514];
                        #pragma unroll
                        for (int nn = 0; nn < 8; nn++) {
                            fma2(acc[0 * 8 + nn], a0, w[nn]);
                            fma2(acc[1 * 8 + nn], a1, w[nn]);
                            fma2(acc[2 * 8 + nn], a2, w[nn]);
                            fma2(acc[3 * 8 + nn], a3, w[nn]);
                            fma2(acc[4 * 8 + nn], a4, w[nn]);
                            fma2(acc[5 * 8 + nn], a5, w[nn]);
                            fma2(acc[6 * 8 + nn], a6, w[nn]);
                            fma2(acc[7 * 8 + nn], a7, w[nn]);
                        }
                    }
                }

                // store prefetched chunk into the other buffer
                if (pf) {
                    float2* b2 = (float2*)((c & 1) ? AbufA : AbufB);
                    #pragma unroll
                    for (int it = 0; it < 4; it++) {
                        const int s = it * NTHR_ + tid;
                        const int k4 = s & 15, m = s >> 4;
                        b2[(2 * k4) * 65 + m]     = make_float2(v[it].x, v[it].y);
                        b2[(2 * k4 + 1) * 65 + m] = make_float2(v[it].z, v[it].w);
                    }
                }
            }
            __syncthreads();

            // ---- fold f32x2 lanes, write partials ----
            #pragma unroll
            for (int mm = 0; mm < 8; mm++)
                #pragma unroll
                for (int nn = 0; nn < 8; nn++) {
                    const unsigned long long a = acc[mm * 8 + nn];
                    const float lo = __uint_as_float((unsigned)(a & 0xffffffffull));
                    const float hi = __uint_as_float((unsigned)(a >> 32));
                    const int n = ng * 8 + nn;
                    const int m = mg * 8 + mm;
                    Pp[(n * 64 + m) * 17 + kg] = lo + hi;
                }
            __syncthreads();

            // ---- reduce 16 k-groups + bias ----
            #pragma unroll
            for (int r = 0; r < 4; r++) {
                const int slot = r * NTHR_ + tid;
                const int n = slot >> 6, m = slot & 63;
                float s = Bs[n];
                #pragma unroll
                for (int q = 0; q < 16; q++) s += Pp[slot * 17 + q];
                Gr[n * 65 + m] = s;
            }
            __syncthreads();

            // ---- pointwise: gates -> c, h ----
            {
                const int jj = tid >> 6, m = tid & 63;
                const float gi = sigf(Gr[jj * 65 + m]);
                const float gf = sigf(Gr[(4 + jj) * 65 + m]);
                const float gc = tanhf(Gr[(8 + jj) * 65 + m]);
                const float go = sigf(Gr[(12 + jj) * 65 + m]);
                const float cv = gf * Cs[jj * 65 + m] + gi * gc;
                Cs[jj * 65 + m] = cv;
                const float hv = go * tanhf(cv);
                Hs[m * 4 + jj] = hv;
                if (t == T_ - 1) cTd[(size_t)m * H_ + j0 + jj] = cv;
            }
            __syncthreads();

            // ---- write h slice to global ----
            if (tid < 64) {
                const float4 hv = *(const float4*)&Hs[tid * 4];
                *(float4*)(hdst + (size_t)t * B_ * H_ + (size_t)tid * H_ + j0) = hv;
                if (t == T_ - 1)
                    *(float4*)(hTd + (size_t)tid * H_ + j0) = hv;
                __threadfence();   // make h visible before the barrier flag
            }

            // ---- grid barrier ----
            __syncthreads();
            ep += GRID_;
            if (tid == 0) {
                atomicAdd(&g_bar, 1);
                while (*((volatile int*)&g_bar) < ep) { }
                __threadfence();
            }
            __syncthreads();
        }
    }
}

extern "C" void kernel_launch(void* const* d_in, const int* in_sizes, int n_in,
                              void* d_out, int out_size) {
    (void)in_sizes; (void)n_in; (void)out_size;
    cudaFuncSetAttribute(lstm_kernel, cudaFuncAttributeMaxDynamicSharedMemorySize,
                         SMEM_BYTES);
    reset_kernel<<<1, 32>>>();
    lstm_kernel<<<GRID_, NTHR_, SMEM_BYTES>>>(
        (const float*)d_in[0],
        (const float*)d_in[1], (const float*)d_in[2],
        (const float*)d_in[3], (const float*)d_in[4],
        (const float*)d_in[5], (const float*)d_in[6],
        (const float*)d_in[7], (const float*)d_in[8],
        (const float*)d_in[9], (const float*)d_in[10],
        (const float*)d_in[11], (const float*)d_in[12],
        (float*)d_out);
}